// round 16
// baseline (speedup 1.0000x reference)
#include <cuda_runtime.h>
#include <cuda_fp16.h>
#include <math.h>
#include <stdint.h>

#define B_  2
#define L_  2048
#define D_  1024
#define H_  16
#define DH_ 64
#define M_  (B_*L_)   // 4096

#define QT_ 64
#define KT_ 64
#define NT_ (L_/KT_)

#define LOG2E 1.4426950408889634f
#define QSCALE (0.125f * LOG2E)

// ---------------- scratch ----------------------------------------------------
__device__ unsigned g_Pf16[4][(size_t)M_*D_/2]; // projections q,k,v,u as f16 pairs (+bias)
__device__ unsigned g_ApU[3][(size_t)M_*D_/2];  // f16x2 permg activations (GEMM input)
__device__ unsigned g_WtU[5][(size_t)D_*D_/2];  // f16x2 transposed+permg weights
__device__ unsigned g_QpU[(size_t)M_*D_/2];     // [bh][l][perm32 pairs], f16, log2e-prescaled
__device__ unsigned g_KpU[(size_t)M_*D_/2];
__device__ unsigned g_VtU[(size_t)M_*D_/2];     // [bh][dh][key pairs perm32], gated V f16x2
__device__ unsigned g_OhpU[(size_t)M_*D_/2];    // attn out, [m][permg pairs] f16
__device__ float g_cos[L_*32];
__device__ float g_sin[L_*32];
__device__ float g_bias[B_*H_*L_];        // log2e * sigmoid(td_gate) * td_emb
__device__ float g_gtab[3*D_];            // action gate table (emb@Wap + bap)
__device__ unsigned g_mbits[B_*L_*(L_/32)];

// ---------------- helpers ----------------------------------------------------
__device__ __forceinline__ float ex2(float x) {
    float r;
    asm("ex2.approx.f32 %0, %1;" : "=f"(r) : "f"(x));
    return r;
}
__device__ __forceinline__ unsigned hfpack(float hi, float lo) {
    unsigned r;
    asm("cvt.rn.f16x2.f32 %0, %1, %2;" : "=r"(r) : "f"(hi), "f"(lo));
    return r;
}

__device__ __forceinline__ void mma_f16(
    float& c0, float& c1, float& c2, float& c3,
    unsigned a0, unsigned a1, unsigned a2, unsigned a3,
    unsigned b0, unsigned b1)
{
    asm volatile(
        "mma.sync.aligned.m16n8k16.row.col.f32.f16.f16.f32 "
        "{%0,%1,%2,%3}, {%4,%5,%6,%7}, {%8,%9}, {%0,%1,%2,%3};\n"
        : "+f"(c0), "+f"(c1), "+f"(c2), "+f"(c3)
        : "r"(a0), "r"(a1), "r"(a2), "r"(a3), "r"(b0), "r"(b1));
}

__device__ __forceinline__ int permg(int p) {     // 16-pair block (GEMM BK=32)
    return (p & 3) * 4 + (p >> 2);
}
__device__ __forceinline__ int perm32p(int p) {   // 32-pair block (attn)
    return (p & 3) * 8 + (p >> 2);
}

__device__ __forceinline__ unsigned s2u(const void* p) {
    return (unsigned)__cvta_generic_to_shared(p);
}
__device__ __forceinline__ void cpa16(void* dst, const void* src) {
    unsigned d = s2u(dst);
    asm volatile("cp.async.cg.shared.global [%0], [%1], 16;\n" :: "r"(d), "l"(src));
}
__device__ __forceinline__ void cpa16u(unsigned d, const void* src) {
    asm volatile("cp.async.cg.shared.global [%0], [%1], 16;\n" :: "r"(d), "l"(src));
}
__device__ __forceinline__ void cpa8(void* dst, const void* src) {
    unsigned d = s2u(dst);
    asm volatile("cp.async.ca.shared.global [%0], [%1], 8;\n" :: "r"(d), "l"(src));
}
__device__ __forceinline__ void cpa_commit() {
    asm volatile("cp.async.commit_group;\n");
}
template<int N> __device__ __forceinline__ void cpa_wait() {
    asm volatile("cp.async.wait_group %0;\n" :: "n"(N));
}

// ---------------- mega preprocessing (block-range dispatch) ------------------
#define PREA_B 1536
#define PREW_B 5120
#define ROPE_B 256
#define BIAS_B 256
#define GTAB_B 12
#define MASK_B 1024
#define MEGA_B (PREA_B + PREW_B + ROPE_B + BIAS_B + GTAB_B + MASK_B)

__global__ __launch_bounds__(256) void mega_pre_kernel(
    const float* __restrict__ q, const float* __restrict__ k, const float* __restrict__ v,
    const float* __restrict__ Wq, const float* __restrict__ Wk,
    const float* __restrict__ Wv, const float* __restrict__ Wu,
    const float* __restrict__ Wo,
    const int* __restrict__ td, const float* __restrict__ td_emb,
    const float* __restrict__ td_gate,
    const float* __restrict__ action_emb, const float* __restrict__ Wap,
    const float* __restrict__ bap,
    const unsigned char* __restrict__ maskb)
{
    __shared__ float t[32][33];
    int bid = blockIdx.x;
    int tid = threadIdx.x;

    if (bid < PREA_B) {
        // activations -> f16 pairs, permg
        int idx = bid * 256 + tid;
        const int per = M_ * D_ / 32;
        int w = idx / per;
        size_t base = (size_t)(idx - w * per) * 32;
        const float* X = (w == 0) ? q : (w == 1) ? k : v;
        float f[32];
#pragma unroll
        for (int i = 0; i < 8; i++)
            *(float4*)&f[i * 4] = *(const float4*)&X[base + i * 4];
        unsigned* O = g_ApU[w] + (base >> 1);
#pragma unroll
        for (int i = 0; i < 4; i++) {
            uint4 o;
            o.x = hfpack(f[2 * (i)      + 1], f[2 * (i)]);
            o.y = hfpack(f[2 * (i + 4)  + 1], f[2 * (i + 4)]);
            o.z = hfpack(f[2 * (i + 8)  + 1], f[2 * (i + 8)]);
            o.w = hfpack(f[2 * (i + 12) + 1], f[2 * (i + 12)]);
            *(uint4*)&O[i * 4] = o;
        }
        return;
    }
    bid -= PREA_B;
    if (bid < PREW_B) {
        // weights -> transpose + f16 pairs + permg
        int wsel = bid >> 10;
        int rem = bid & 1023;
        int k0 = (rem & 31) * 32, n0 = (rem >> 5) * 32;
        const float* W = (wsel == 0) ? Wq : (wsel == 1) ? Wk :
                         (wsel == 2) ? Wv : (wsel == 3) ? Wu : Wo;
#pragma unroll
        for (int i = 0; i < 4; i++) {
            int r = (tid >> 5) + i * 8, c = tid & 31;
            t[r][c] = W[(size_t)(k0 + r) * D_ + n0 + c];
        }
        __syncthreads();
#pragma unroll
        for (int j = 0; j < 2; j++) {
            int item = tid + j * 256;
            int ty = item >> 4, tx = item & 15;
            unsigned val = hfpack(t[2 * tx + 1][ty], t[2 * tx][ty]);
            g_WtU[wsel][(size_t)(n0 + ty) * (D_ / 2) + (k0 >> 1) + permg(tx)] = val;
        }
        return;
    }
    bid -= PREW_B;
    if (bid < ROPE_B) {
        int idx = bid * 256 + tid;
        int l = idx >> 5, j = idx & 31;
        double invf = exp(-((double)(2 * j) / 64.0) * log(10000.0));
        double a = (double)l * invf;
        g_cos[idx] = (float)cos(a);
        g_sin[idx] = (float)sin(a);
        return;
    }
    bid -= ROPE_B;
    if (bid < BIAS_B) {
        int idx = bid * 256 + tid;
        int kk = idx & (L_ - 1);
        int h = (idx >> 11) & 15;
        int b = idx >> 15;
        float sg = 1.f / (1.f + __expf(-td_gate[0]));
        int tv = min(max(td[b * L_ + kk], 0), 127);
        g_bias[idx] = LOG2E * sg * td_emb[tv * H_ + h];
        return;
    }
    bid -= BIAS_B;
    if (bid < GTAB_B) {
        int idx = bid * 256 + tid;
        if (idx < 3 * D_) {
            int a = idx >> 10, d = idx & 1023;
            float g = bap[d];
#pragma unroll
            for (int j = 0; j < 16; j++)
                g = fmaf(action_emb[a * 16 + j], Wap[j * D_ + d], g);
            g_gtab[idx] = g;
        }
        return;
    }
    bid -= GTAB_B;
    {
        int idx = bid * 256 + tid;
        int kg = idx & 63;
        int qq = (idx >> 6) & (L_ - 1);
        int b  = idx >> 17;
        bool bytes = (maskb[0] != 0 && maskb[1] != 0);
        unsigned bits = 0;
        if (bytes) {
            const uint4* p = (const uint4*)(maskb + ((size_t)b * L_ + qq) * L_ + kg * 32);
            uint4 u0 = p[0], u1 = p[1];
            unsigned ws[8] = {u0.x, u0.y, u0.z, u0.w, u1.x, u1.y, u1.z, u1.w};
#pragma unroll
            for (int i = 0; i < 8; i++)
#pragma unroll
                for (int j = 0; j < 4; j++)
                    bits |= (((ws[i] >> (8 * j)) & 0xffu) ? 1u : 0u) << (i * 4 + j);
        } else {
            const uint4* p = (const uint4*)((const unsigned*)maskb + ((size_t)b * L_ + qq) * L_ + kg * 32);
#pragma unroll
            for (int i = 0; i < 8; i++) {
                uint4 vv = p[i];
                bits |= (vv.x ? 1u : 0u) << (i * 4 + 0);
                bits |= (vv.y ? 1u : 0u) << (i * 4 + 1);
                bits |= (vv.z ? 1u : 0u) << (i * 4 + 2);
                bits |= (vv.w ? 1u : 0u) << (i * 4 + 3);
            }
        }
        g_mbits[idx] = bits;
    }
}

// ---------------- f16 GEMM: BK=32, 4-stage unrolled pipeline ----------------
#define GSB2 4096   // uints per stage block

template<int MODE>
__global__ __launch_bounds__(256, 2) void gemm4_kernel(
    const float* __restrict__ bq, const float* __restrict__ bk,
    const float* __restrict__ bv, const float* __restrict__ bu,
    const float* __restrict__ bo, float* __restrict__ outp)
{
    extern __shared__ unsigned usm[];
    int tid = threadIdx.x;
    int w = tid >> 5, lane = tid & 31;
    int wm = w & 3, wn = w >> 2;
    int grp = lane >> 2, tig = lane & 3;

    int n0 = blockIdx.x * 128;
    int m0 = blockIdx.y * 128;

    const unsigned* A;
    const unsigned* Wt;
    const float* bias;
    unsigned* out16 = nullptr;
    float* outf = nullptr;
    if (MODE == 0) {
        int wsel = blockIdx.z;
        A     = g_ApU[wsel == 3 ? 0 : wsel];     // U uses query
        Wt    = g_WtU[wsel];
        bias  = (wsel == 0) ? bq : (wsel == 1) ? bk : (wsel == 2) ? bv : bu;
        out16 = g_Pf16[wsel];
    } else {
        A = g_OhpU; Wt = g_WtU[4]; bias = bo; outf = outp;
    }

    int r0f = tid >> 2,          s0f = (tid & 3) * 4;
    int r1f = (tid + 256) >> 2;
    const unsigned* pA0 = &A [(size_t)(m0 + r0f) * (D_ / 2) + s0f];
    const unsigned* pA1 = &A [(size_t)(m0 + r1f) * (D_ / 2) + s0f];
    const unsigned* pB0 = &Wt[(size_t)(n0 + r0f) * (D_ / 2) + s0f];
    const unsigned* pB1 = &Wt[(size_t)(n0 + r1f) * (D_ / 2) + s0f];
    unsigned base_u = s2u(usm);
    unsigned uA0 = base_u + (r0f * 16 + s0f) * 4;
    unsigned uA1 = base_u + (r1f * 16 + s0f) * 4;
    unsigned uB0 = uA0 + 2048 * 4;
    unsigned uB1 = uA1 + 2048 * 4;

    int aoff = (wm * 32 + grp) * 16 + tig * 4;
    int boff = (wn * 64 + grp) * 16 + tig * 4;

    float acc[2][8][4];
#pragma unroll
    for (int mt = 0; mt < 2; mt++)
#pragma unroll
        for (int nt = 0; nt < 8; nt++)
#pragma unroll
            for (int r = 0; r < 4; r++) acc[mt][nt][r] = 0.f;

#pragma unroll
    for (int p = 0; p < 3; p++) {
        cpa16u(uA0 + p * 16384, pA0); cpa16u(uA1 + p * 16384, pA1);
        cpa16u(uB0 + p * 16384, pB0); cpa16u(uB1 + p * 16384, pB1);
        cpa_commit();
        pA0 += 16; pA1 += 16; pB0 += 16; pB1 += 16;
    }

    int ktf = 48;
    for (int tt = 0; tt < 8; tt++) {
#pragma unroll
        for (int j = 0; j < 4; j++) {
            cpa_wait<2>();
            __syncthreads();

            if (ktf < D_ / 2) {
                const unsigned so = ((j + 3) & 3) * 16384;
                cpa16u(uA0 + so, pA0); cpa16u(uA1 + so, pA1);
                cpa16u(uB0 + so, pB0); cpa16u(uB1 + so, pB1);
                pA0 += 16; pA1 += 16; pB0 += 16; pB1 += 16;
            }
            cpa_commit();
            ktf += 16;

            const unsigned* As = usm + j * GSB2;
            const unsigned* Bs = As + 2048;

            uint4 av[2], ah[2];
#pragma unroll
            for (int mt = 0; mt < 2; mt++) {
                av[mt] = *(const uint4*)&As[aoff + mt * 256];
                ah[mt] = *(const uint4*)&As[aoff + mt * 256 + 128];
            }
            uint4 bw = *(const uint4*)&Bs[boff];
#pragma unroll
            for (int nt = 0; nt < 8; nt++) {
                uint4 bwn;
                if (nt < 7) bwn = *(const uint4*)&Bs[boff + (nt + 1) * 128];
#pragma unroll
                for (int mt = 0; mt < 2; mt++) {
                    mma_f16(acc[mt][nt][0], acc[mt][nt][1], acc[mt][nt][2], acc[mt][nt][3],
                            av[mt].x, ah[mt].x, av[mt].y, ah[mt].y, bw.x, bw.y);
                    mma_f16(acc[mt][nt][0], acc[mt][nt][1], acc[mt][nt][2], acc[mt][nt][3],
                            av[mt].z, ah[mt].z, av[mt].w, ah[mt].w, bw.z, bw.w);
                }
                bw = bwn;
            }
        }
    }

#pragma unroll
    for (int mt = 0; mt < 2; mt++) {
        int row = m0 + wm * 32 + mt * 16 + grp;
#pragma unroll
        for (int nt = 0; nt < 8; nt++) {
            int col = n0 + wn * 64 + nt * 8 + tig * 2;
            float2 b01 = make_float2(bias[col], bias[col + 1]);
            if (MODE == 0) {
                out16[(size_t)row * (D_ / 2) + (col >> 1)] =
                    hfpack(acc[mt][nt][1] + b01.y, acc[mt][nt][0] + b01.x);
                out16[(size_t)(row + 8) * (D_ / 2) + (col >> 1)] =
                    hfpack(acc[mt][nt][3] + b01.y, acc[mt][nt][2] + b01.x);
            } else {
                *(float2*)&outf[(size_t)row * D_ + col] =
                    make_float2(acc[mt][nt][0] + b01.x, acc[mt][nt][1] + b01.y);
                *(float2*)&outf[(size_t)(row + 8) * D_ + col] =
                    make_float2(acc[mt][nt][2] + b01.x, acc[mt][nt][3] + b01.y);
            }
        }
    }
}

// ---------------- prep: tiled RoPE/gate -> f16 pairs (reads f16 proj) -------
__global__ __launch_bounds__(256) void prep_kernel(const int* __restrict__ action_ids)
{
    __shared__ float Vs[64 * 65];
    int tid = threadIdx.x;
    int l0 = blockIdx.x * 64;
    int bh = blockIdx.y;
    int b = bh >> 4, h = bh & 15;

#pragma unroll
    for (int u = 0; u < 4; u++) {
        int fid = tid + u * 256;
        int r = fid >> 4, c4 = (fid & 15) * 4;
        int l = l0 + r;
        int m = b * L_ + l;
        size_t base2 = (size_t)m * (D_ / 2) + h * 32;
        int pp = c4 >> 1;
        int pq = (c4 ^ 32) >> 1;

        uint2 qU  = *(const uint2*)&g_Pf16[0][base2 + pp];
        uint2 kU  = *(const uint2*)&g_Pf16[1][base2 + pp];
        uint2 vU  = *(const uint2*)&g_Pf16[2][base2 + pp];
        uint2 uU  = *(const uint2*)&g_Pf16[3][base2 + pp];
        uint2 qpU = *(const uint2*)&g_Pf16[0][base2 + pq];
        uint2 kpU = *(const uint2*)&g_Pf16[1][base2 + pq];

        float2 qa = __half22float2(*(const __half2*)&qU.x);
        float2 qb = __half22float2(*(const __half2*)&qU.y);
        float2 ka = __half22float2(*(const __half2*)&kU.x);
        float2 kb = __half22float2(*(const __half2*)&kU.y);
        float2 va = __half22float2(*(const __half2*)&vU.x);
        float2 vb = __half22float2(*(const __half2*)&vU.y);
        float2 ua = __half22float2(*(const __half2*)&uU.x);
        float2 ub = __half22float2(*(const __half2*)&uU.y);
        float2 qpa = __half22float2(*(const __half2*)&qpU.x);
        float2 qpb = __half22float2(*(const __half2*)&qpU.y);
        float2 kpa = __half22float2(*(const __half2*)&kpU.x);
        float2 kpb = __half22float2(*(const __half2*)&kpU.y);

        int aid = action_ids[m];
        float4 gt = *(const float4*)&g_gtab[aid * D_ + h * 64 + c4];

        float ga0 = 1.f / (1.f + __expf(-(ua.x + gt.x)));
        float ga1 = 1.f / (1.f + __expf(-(ua.y + gt.y)));
        float ga2 = 1.f / (1.f + __expf(-(ub.x + gt.z)));
        float ga3 = 1.f / (1.f + __expf(-(ub.y + gt.w)));
        Vs[r * 65 + c4 + 0] = va.x * ga0;
        Vs[r * 65 + c4 + 1] = va.y * ga1;
        Vs[r * 65 + c4 + 2] = vb.x * ga2;
        Vs[r * 65 + c4 + 3] = vb.y * ga3;

        float sgn = (c4 < 32) ? -1.f : 1.f;
        int ci = l * 32 + (c4 >> 1);
        float c0 = g_cos[ci],     s0 = g_sin[ci];
        float c1 = g_cos[ci + 1], s1 = g_sin[ci + 1];

        float q0 = (qa.x * c0 + sgn * qpa.x * s0) * QSCALE;
        float q1 = (qa.y * c0 + sgn * qpa.y * s0) * QSCALE;
        float q2 = (qb.x * c1 + sgn * qpb.x * s1) * QSCALE;
        float q3 = (qb.y * c1 + sgn * qpb.y * s1) * QSCALE;
        float k0 = ka.x * c0 + sgn * kpa.x * s0;
        float k1 = ka.y * c0 + sgn * kpa.y * s0;
        float k2 = kb.x * c1 + sgn * kpb.x * s1;
        float k3 = kb.y * c1 + sgn * kpb.y * s1;

        size_t qb32 = ((size_t)bh * L_ + l) * 32;
        g_QpU[qb32 + perm32p(pp)]     = hfpack(q1, q0);
        g_QpU[qb32 + perm32p(pp + 1)] = hfpack(q3, q2);
        g_KpU[qb32 + perm32p(pp)]     = hfpack(k1, k0);
        g_KpU[qb32 + perm32p(pp + 1)] = hfpack(k3, k2);
    }
    __syncthreads();

    int w = tid >> 5, lane = tid & 31;
#pragma unroll
    for (int i = 0; i < 8; i++) {
        int dh = w * 8 + i;
        unsigned* orow = &g_VtU[((size_t)bh * DH_ + dh) * (L_ / 2) + (l0 >> 1)];
        unsigned val = hfpack(Vs[(2 * lane + 1) * 65 + dh], Vs[(2 * lane) * 65 + dh]);
        orow[perm32p(lane)] = val;
    }
}

// ---------------- tensor-core flash attention (f16, QT=64, 128 threads) -----
#define KS_O 0
#define KV_STG (64*36)
#define VT_O (2*KV_STG)
#define BI_O (VT_O + 2*KV_STG)
#define MK_O (BI_O + 2*64)
#define SMEMF (MK_O + 2*128)

__device__ __forceinline__ void stage_fill(
    unsigned* usm, int s, int tid, int bh, int b, int q0, int k0)
{
    unsigned* KsS = usm + KS_O + s * KV_STG;
    unsigned* VtS = usm + VT_O + s * KV_STG;
#pragma unroll
    for (int u = 0; u < 4; u++) {
        int cid = tid + u * 128;
        int row = cid >> 3, seg = (cid & 7) * 4;
        cpa16(&KsS[row * 36 + seg],
              &g_KpU[((size_t)bh * L_ + k0 + row) * 32 + seg]);
        cpa16(&VtS[row * 36 + seg],
              &g_VtU[((size_t)bh * DH_ + row) * (L_ / 2) + (k0 >> 1) + seg]);
    }
    if (tid < 16)
        cpa16(usm + BI_O + s * 64 + tid * 4, &g_bias[(size_t)bh * L_ + k0 + tid * 4]);
    if (tid < 64) {
        unsigned* mdst = usm + MK_O + s * 128 + tid * 2;
        cpa8(mdst, &g_mbits[((size_t)b * L_ + q0 + tid) * (L_ / 32) + (k0 >> 5)]);
    }
}

__global__ __launch_bounds__(128, 4) void attn_kernel() {
    extern __shared__ unsigned usm[];

    int tid = threadIdx.x;
    int w = tid >> 5, lane = tid & 31;
    int grp = lane >> 2, tig = lane & 3;
    int q0 = blockIdx.x * QT_;
    int bh = blockIdx.y;
    int b = bh >> 4, h = bh & 15;
    int w16 = w * 16;

    unsigned af[4][4];
    {
        const unsigned* q0p = &g_QpU[((size_t)bh * L_ + q0 + w16 + grp) * 32 + tig * 8];
        const unsigned* q1p = &g_QpU[((size_t)bh * L_ + q0 + w16 + grp + 8) * 32 + tig * 8];
        uint4 qa = *(const uint4*)q0p;
        uint4 qb = *(const uint4*)(q0p + 4);
        uint4 qc = *(const uint4*)q1p;
        uint4 qd = *(const uint4*)(q1p + 4);
        af[0][0] = qa.x; af[0][1] = qc.x; af[0][2] = qa.y; af[0][3] = qc.y;
        af[1][0] = qa.z; af[1][1] = qc.z; af[1][2] = qa.w; af[1][3] = qc.w;
        af[2][0] = qb.x; af[2][1] = qd.x; af[2][2] = qb.y; af[2][3] = qd.y;
        af[3][0] = qb.z; af[3][1] = qd.z; af[3][2] = qb.w; af[3][3] = qd.w;
    }

    float o[8][4];
#pragma unroll
    for (int nf = 0; nf < 8; nf++)
#pragma unroll
        for (int r = 0; r < 4; r++) o[nf][r] = 0.f;
    float l0r = 0.f, l1r = 0.f;

    stage_fill(usm, 0, tid, bh, b, q0, 0);
    cpa_commit();

    for (int t = 0; t < NT_; t++) {
        if (t + 1 < NT_) {
            stage_fill(usm, (t + 1) & 1, tid, bh, b, q0, (t + 1) * KT_);
            cpa_commit();
            cpa_wait<1>();
        } else {
            cpa_wait<0>();
        }
        __syncthreads();

        int s = t & 1;
        const unsigned* KsS = usm + KS_O + s * KV_STG;
        const unsigned* VtU = usm + VT_O + s * KV_STG;
        const float* biasS = (const float*)(usm + BI_O + s * 64);
        const unsigned* mk = usm + MK_O + s * 128;

        unsigned mr0lo = mk[(w16 + grp) * 2],     mr0hi = mk[(w16 + grp) * 2 + 1];
        unsigned mr1lo = mk[(w16 + grp + 8) * 2], mr1hi = mk[(w16 + grp + 8) * 2 + 1];

        // ---- scores (f16 m16n8k16), rolling K prefetch ----
        float sc[8][4];
        uint4 kv1 = *(const uint4*)&KsS[grp * 36 + tig * 8];
        uint4 kv2 = *(const uint4*)&KsS[grp * 36 + tig * 8 + 4];
#pragma unroll
        for (int nf = 0; nf < 8; nf++) {
            uint4 n1, n2;
            if (nf < 7) {
                const unsigned* kpn = &KsS[((nf + 1) * 8 + grp) * 36 + tig * 8];
                n1 = *(const uint4*)kpn;
                n2 = *(const uint4*)(kpn + 4);
            }
            sc[nf][0] = 0.f; sc[nf][1] = 0.f; sc[nf][2] = 0.f; sc[nf][3] = 0.f;
            mma_f16(sc[nf][0], sc[nf][1], sc[nf][2], sc[nf][3],
                    af[0][0], af[0][1], af[0][2], af[0][3], kv1.x, kv1.y);
            mma_f16(sc[nf][0], sc[nf][1], sc[nf][2], sc[nf][3],
                    af[1][0], af[1][1], af[1][2], af[1][3], kv1.z, kv1.w);
            mma_f16(sc[nf][0], sc[nf][1], sc[nf][2], sc[nf][3],
                    af[2][0], af[2][1], af[2][2], af[2][3], kv2.x, kv2.y);
            mma_f16(sc[nf][0], sc[nf][1], sc[nf][2], sc[nf][3],
                    af[3][0], af[3][1], af[3][2], af[3][3], kv2.z, kv2.w);
            kv1 = n1; kv2 = n2;
        }

        // ---- softmax -> PV, chunk-interleaved; fast path for all-ones mask ----
        bool full = (mr0lo & mr0hi & mr1lo & mr1hi) == 0xffffffffu;
        if (full) {
#pragma unroll
            for (int c = 0; c < 4; c++) {
                int nA = 2 * c, nB = 2 * c + 1;
                float2 bbA = *(const float2*)&biasS[nA * 8 + tig * 2];
                float2 bbB = *(const float2*)&biasS[nB * 8 + tig * 2];
                float pA0 = ex2(sc[nA][0] + bbA.x);
                float pA1 = ex2(sc[nA][1] + bbA.y);
                float pA2 = ex2(sc[nA][2] + bbA.x);
                float pA3 = ex2(sc[nA][3] + bbA.y);
                float pB0 = ex2(sc[nB][0] + bbB.x);
                float pB1 = ex2(sc[nB][1] + bbB.y);
                float pB2 = ex2(sc[nB][2] + bbB.x);
                float pB3 = ex2(sc[nB][3] + bbB.y);
                l0r += (pA0 + pA1) + (pB0 + pB1);
                l1r += (pA2 + pA3) + (pB2 + pB3);
                unsigned f0 = hfpack(pA1, pA0);
                unsigned f1 = hfpack(pA3, pA2);
                unsigned f2 = hfpack(pB1, pB0);
                unsigned f3 = hfpack(pB3, pB2);
#pragma unroll
                for (int nf = 0; nf < 8; nf++) {
                    uint2 v2 = *(const uint2*)&VtU[(nf * 8 + grp) * 36 + tig * 8 + 2 * c];
                    mma_f16(o[nf][0], o[nf][1], o[nf][2], o[nf][3],
                            f0, f1, f2, f3, v2.x, v2.y);
                }
            }
        } else {
#pragma unroll
            for (int c = 0; c < 4; c++) {
                int nA = 2 * c, nB = 2 * c + 1;
                float2 bbA = *(const float2*)&biasS[nA * 8 + tig * 2];
                float2 bbB = *(const float2*)&biasS[nB * 8 + tig * 2];
                int bpA = (nA & 3) * 8 + tig * 2;
                int bpB = (nB & 3) * 8 + tig * 2;
                unsigned mA0 = ((nA < 4) ? mr0lo : mr0hi) >> bpA;
                unsigned mA1 = ((nA < 4) ? mr1lo : mr1hi) >> bpA;
                unsigned mB0 = ((nB < 4) ? mr0lo : mr0hi) >> bpB;
                unsigned mB1 = ((nB < 4) ? mr1lo : mr1hi) >> bpB;

                float pA0 = (mA0 & 1u) ? ex2(sc[nA][0] + bbA.x) : 0.f;
                float pA1 = (mA0 & 2u) ? ex2(sc[nA][1] + bbA.y) : 0.f;
                float pA2 = (mA1 & 1u) ? ex2(sc[nA][2] + bbA.x) : 0.f;
                float pA3 = (mA1 & 2u) ? ex2(sc[nA][3] + bbA.y) : 0.f;
                float pB0 = (mB0 & 1u) ? ex2(sc[nB][0] + bbB.x) : 0.f;
                float pB1 = (mB0 & 2u) ? ex2(sc[nB][1] + bbB.y) : 0.f;
                float pB2 = (mB1 & 1u) ? ex2(sc[nB][2] + bbB.x) : 0.f;
                float pB3 = (mB1 & 2u) ? ex2(sc[nB][3] + bbB.y) : 0.f;

                l0r += (pA0 + pA1) + (pB0 + pB1);
                l1r += (pA2 + pA3) + (pB2 + pB3);
                unsigned f0 = hfpack(pA1, pA0);
                unsigned f1 = hfpack(pA3, pA2);
                unsigned f2 = hfpack(pB1, pB0);
                unsigned f3 = hfpack(pB3, pB2);
#pragma unroll
                for (int nf = 0; nf < 8; nf++) {
                    uint2 v2 = *(const uint2*)&VtU[(nf * 8 + grp) * 36 + tig * 8 + 2 * c];
                    mma_f16(o[nf][0], o[nf][1], o[nf][2], o[nf][3],
                            f0, f1, f2, f3, v2.x, v2.y);
                }
            }
        }
        __syncthreads();
    }

    // ---- final row-sum reduction across the quad, then normalize ----
    l0r += __shfl_xor_sync(0xffffffffu, l0r, 1);
    l0r += __shfl_xor_sync(0xffffffffu, l0r, 2);
    l1r += __shfl_xor_sync(0xffffffffu, l1r, 1);
    l1r += __shfl_xor_sync(0xffffffffu, l1r, 2);
    float inv0 = 1.f / l0r, inv1 = 1.f / l1r;

    int l0i = q0 + w16 + grp;
    size_t r0 = ((size_t)(b * L_) + l0i) * (D_ / 2) + h * 32;
    size_t r1 = ((size_t)(b * L_) + l0i + 8) * (D_ / 2) + h * 32;
#pragma unroll
    for (int nf = 0; nf < 8; nf++) {
        int p = nf * 4 + tig;
        int pos = (p & 16) + permg(p & 15);
        g_OhpU[r0 + pos] = hfpack(o[nf][1] * inv0, o[nf][0] * inv0);
        g_OhpU[r1 + pos] = hfpack(o[nf][3] * inv1, o[nf][2] * inv1);
    }
}

// ---------------- launch -----------------------------------------------------
extern "C" void kernel_launch(void* const* d_in, const int* in_sizes, int n_in,
                              void* d_out, int out_size)
{
    const float* query      = (const float*)d_in[0];
    const float* key        = (const float*)d_in[1];
    const float* value      = (const float*)d_in[2];
    const unsigned char* am = (const unsigned char*)d_in[3];
    const int*   action_ids = (const int*)d_in[4];
    const int*   time_delta = (const int*)d_in[5];
    const float* Wq = (const float*)d_in[6];
    const float* bq = (const float*)d_in[7];
    const float* Wk = (const float*)d_in[8];
    const float* bk = (const float*)d_in[9];
    const float* Wv = (const float*)d_in[10];
    const float* bv = (const float*)d_in[11];
    const float* Wu = (const float*)d_in[12];
    const float* bu = (const float*)d_in[13];
    const float* Wo = (const float*)d_in[14];
    const float* bo = (const float*)d_in[15];
    const float* action_emb = (const float*)d_in[16];
    const float* Wap = (const float*)d_in[17];
    const float* bap = (const float*)d_in[18];
    const float* td_emb  = (const float*)d_in[19];
    const float* td_gate = (const float*)d_in[20];
    float* out = (float*)d_out;

    const int gemm_smem = 4 * GSB2 * (int)sizeof(unsigned);
    cudaFuncSetAttribute(gemm4_kernel<0>, cudaFuncAttributeMaxDynamicSharedMemorySize, gemm_smem);
    cudaFuncSetAttribute(gemm4_kernel<1>, cudaFuncAttributeMaxDynamicSharedMemorySize, gemm_smem);

    // launch order: mega_pre(1), gemm<0>(2), prep(3), attn(4 <- profiled), gemm<1>(5)
    mega_pre_kernel<<<MEGA_B, 256>>>(query, key, value, Wq, Wk, Wv, Wu, Wo,
                                     time_delta, td_emb, td_gate,
                                     action_emb, Wap, bap, am);

    gemm4_kernel<0><<<dim3(8, 32, 4), 256, gemm_smem>>>(bq, bk, bv, bu, bo, nullptr);

    prep_kernel<<<dim3(L_ / 64, B_ * H_), 256>>>(action_ids);

    const int attn_smem = SMEMF * (int)sizeof(unsigned);
    cudaFuncSetAttribute(attn_kernel, cudaFuncAttributeMaxDynamicSharedMemorySize, attn_smem);
    attn_kernel<<<dim3(L_ / QT_, B_ * H_), 128, attn_smem>>>();

    gemm4_kernel<1><<<dim3(8, 32, 1), 256, gemm_smem>>>(bq, bk, bv, bu, bo, out);
}

// round 17
// speedup vs baseline: 1.4583x; 1.4583x over previous
#include <cuda_runtime.h>
#include <math.h>
#include <stdint.h>

#define B_  2
#define L_  2048
#define D_  1024
#define H_  16
#define DH_ 64
#define M_  (B_*L_)   // 4096

#define QT_ 128
#define KT_ 64
#define NT_ (L_/KT_)

#define LOG2E 1.4426950408889634f
#define QSCALE (0.125f * LOG2E)

// ---------------- scratch ----------------------------------------------------
__device__ float    g_P[4][(size_t)M_*D_];     // raw projections q,k,v,u (fp32+bias)
__device__ unsigned g_ApU[3][(size_t)M_*D_/2]; // f16x2 pair-permuted activations
__device__ unsigned g_WtU[5][(size_t)D_*D_/2]; // f16x2 transposed+permuted weights
__device__ unsigned g_QpU[(size_t)M_*D_/2];    // [bh][l][perm32 pairs], f16, log2e-prescaled
__device__ unsigned g_KpU[(size_t)M_*D_/2];
__device__ unsigned g_VtU[(size_t)M_*D_/2];    // [bh][dh][key pairs perm32], gated V f16x2
__device__ unsigned g_OhpU[(size_t)M_*D_/2];   // attn out, [m][permg pairs] f16
__device__ float g_cos[L_*32];
__device__ float g_sin[L_*32];
__device__ float g_bias[B_*H_*L_];        // log2e * sigmoid(td_gate) * td_emb
__device__ float g_gtab[3*D_];            // action gate table (emb@Wap + bap)
__device__ unsigned g_mbits[B_*L_*(L_/32)];

// ---------------- helpers ----------------------------------------------------
__device__ __forceinline__ float ex2(float x) {
    float r;
    asm("ex2.approx.f32 %0, %1;" : "=f"(r) : "f"(x));
    return r;
}
__device__ __forceinline__ unsigned hfpack(float hi, float lo) {
    unsigned r;
    asm("cvt.rn.f16x2.f32 %0, %1, %2;" : "=r"(r) : "f"(hi), "f"(lo));
    return r;
}

__device__ __forceinline__ void mma_f16(
    float& c0, float& c1, float& c2, float& c3,
    unsigned a0, unsigned a1, unsigned a2, unsigned a3,
    unsigned b0, unsigned b1)
{
    asm volatile(
        "mma.sync.aligned.m16n8k16.row.col.f32.f16.f16.f32 "
        "{%0,%1,%2,%3}, {%4,%5,%6,%7}, {%8,%9}, {%0,%1,%2,%3};\n"
        : "+f"(c0), "+f"(c1), "+f"(c2), "+f"(c3)
        : "r"(a0), "r"(a1), "r"(a2), "r"(a3), "r"(b0), "r"(b1));
}

__device__ __forceinline__ int permg(int p) {     // 16-pair block (GEMM BK=32)
    return (p & 3) * 4 + (p >> 2);
}
__device__ __forceinline__ int perm32p(int p) {   // 32-pair block (attn)
    return (p & 3) * 8 + (p >> 2);
}

__device__ __forceinline__ unsigned s2u(const void* p) {
    return (unsigned)__cvta_generic_to_shared(p);
}
__device__ __forceinline__ void cpa16(void* dst, const void* src) {
    unsigned d = s2u(dst);
    asm volatile("cp.async.cg.shared.global [%0], [%1], 16;\n" :: "r"(d), "l"(src));
}
__device__ __forceinline__ void cpa16u(unsigned d, const void* src) {
    asm volatile("cp.async.cg.shared.global [%0], [%1], 16;\n" :: "r"(d), "l"(src));
}
__device__ __forceinline__ void cpa8(void* dst, const void* src) {
    unsigned d = s2u(dst);
    asm volatile("cp.async.ca.shared.global [%0], [%1], 8;\n" :: "r"(d), "l"(src));
}
__device__ __forceinline__ void cpa_commit() {
    asm volatile("cp.async.commit_group;\n");
}
template<int N> __device__ __forceinline__ void cpa_wait() {
    asm volatile("cp.async.wait_group %0;\n" :: "n"(N));
}

// ---------------- mega preprocessing (block-range dispatch) ------------------
#define PREA_B 1536
#define PREW_B 5120
#define ROPE_B 256
#define BIAS_B 256
#define GTAB_B 12
#define MASK_B 1024
#define MEGA_B (PREA_B + PREW_B + ROPE_B + BIAS_B + GTAB_B + MASK_B)

__global__ __launch_bounds__(256) void mega_pre_kernel(
    const float* __restrict__ q, const float* __restrict__ k, const float* __restrict__ v,
    const float* __restrict__ Wq, const float* __restrict__ Wk,
    const float* __restrict__ Wv, const float* __restrict__ Wu,
    const float* __restrict__ Wo,
    const int* __restrict__ td, const float* __restrict__ td_emb,
    const float* __restrict__ td_gate,
    const float* __restrict__ action_emb, const float* __restrict__ Wap,
    const float* __restrict__ bap,
    const unsigned char* __restrict__ maskb)
{
    __shared__ float t[32][33];
    int bid = blockIdx.x;
    int tid = threadIdx.x;

    if (bid < PREA_B) {
        int idx = bid * 256 + tid;
        const int per = M_ * D_ / 32;
        int w = idx / per;
        size_t base = (size_t)(idx - w * per) * 32;
        const float* X = (w == 0) ? q : (w == 1) ? k : v;
        float f[32];
#pragma unroll
        for (int i = 0; i < 8; i++)
            *(float4*)&f[i * 4] = *(const float4*)&X[base + i * 4];
        unsigned* O = g_ApU[w] + (base >> 1);
#pragma unroll
        for (int i = 0; i < 4; i++) {
            uint4 o;
            o.x = hfpack(f[2 * (i)      + 1], f[2 * (i)]);
            o.y = hfpack(f[2 * (i + 4)  + 1], f[2 * (i + 4)]);
            o.z = hfpack(f[2 * (i + 8)  + 1], f[2 * (i + 8)]);
            o.w = hfpack(f[2 * (i + 12) + 1], f[2 * (i + 12)]);
            *(uint4*)&O[i * 4] = o;
        }
        return;
    }
    bid -= PREA_B;
    if (bid < PREW_B) {
        int wsel = bid >> 10;
        int rem = bid & 1023;
        int k0 = (rem & 31) * 32, n0 = (rem >> 5) * 32;
        const float* W = (wsel == 0) ? Wq : (wsel == 1) ? Wk :
                         (wsel == 2) ? Wv : (wsel == 3) ? Wu : Wo;
#pragma unroll
        for (int i = 0; i < 4; i++) {
            int r = (tid >> 5) + i * 8, c = tid & 31;
            t[r][c] = W[(size_t)(k0 + r) * D_ + n0 + c];
        }
        __syncthreads();
#pragma unroll
        for (int j = 0; j < 2; j++) {
            int item = tid + j * 256;
            int ty = item >> 4, tx = item & 15;
            unsigned val = hfpack(t[2 * tx + 1][ty], t[2 * tx][ty]);
            g_WtU[wsel][(size_t)(n0 + ty) * (D_ / 2) + (k0 >> 1) + permg(tx)] = val;
        }
        return;
    }
    bid -= PREW_B;
    if (bid < ROPE_B) {
        int idx = bid * 256 + tid;
        int l = idx >> 5, j = idx & 31;
        double invf = exp(-((double)(2 * j) / 64.0) * log(10000.0));
        double a = (double)l * invf;
        g_cos[idx] = (float)cos(a);
        g_sin[idx] = (float)sin(a);
        return;
    }
    bid -= ROPE_B;
    if (bid < BIAS_B) {
        int idx = bid * 256 + tid;
        int kk = idx & (L_ - 1);
        int h = (idx >> 11) & 15;
        int b = idx >> 15;
        float sg = 1.f / (1.f + __expf(-td_gate[0]));
        int tv = min(max(td[b * L_ + kk], 0), 127);
        g_bias[idx] = LOG2E * sg * td_emb[tv * H_ + h];
        return;
    }
    bid -= BIAS_B;
    if (bid < GTAB_B) {
        int idx = bid * 256 + tid;
        if (idx < 3 * D_) {
            int a = idx >> 10, d = idx & 1023;
            float g = bap[d];
#pragma unroll
            for (int j = 0; j < 16; j++)
                g = fmaf(action_emb[a * 16 + j], Wap[j * D_ + d], g);
            g_gtab[idx] = g;
        }
        return;
    }
    bid -= GTAB_B;
    {
        int idx = bid * 256 + tid;
        int kg = idx & 63;
        int qq = (idx >> 6) & (L_ - 1);
        int b  = idx >> 17;
        bool bytes = (maskb[0] != 0 && maskb[1] != 0);
        unsigned bits = 0;
        if (bytes) {
            const uint4* p = (const uint4*)(maskb + ((size_t)b * L_ + qq) * L_ + kg * 32);
            uint4 u0 = p[0], u1 = p[1];
            unsigned ws[8] = {u0.x, u0.y, u0.z, u0.w, u1.x, u1.y, u1.z, u1.w};
#pragma unroll
            for (int i = 0; i < 8; i++)
#pragma unroll
                for (int j = 0; j < 4; j++)
                    bits |= (((ws[i] >> (8 * j)) & 0xffu) ? 1u : 0u) << (i * 4 + j);
        } else {
            const uint4* p = (const uint4*)((const unsigned*)maskb + ((size_t)b * L_ + qq) * L_ + kg * 32);
#pragma unroll
            for (int i = 0; i < 8; i++) {
                uint4 vv = p[i];
                bits |= (vv.x ? 1u : 0u) << (i * 4 + 0);
                bits |= (vv.y ? 1u : 0u) << (i * 4 + 1);
                bits |= (vv.z ? 1u : 0u) << (i * 4 + 2);
                bits |= (vv.w ? 1u : 0u) << (i * 4 + 3);
            }
        }
        g_mbits[idx] = bits;
    }
}

// ---------------- f16 GEMM: BK=32, 4-stage unrolled pipeline ----------------
#define GSB2 4096   // uints per stage block

template<int MODE>
__global__ __launch_bounds__(256, 2) void gemm4_kernel(
    const float* __restrict__ bq, const float* __restrict__ bk,
    const float* __restrict__ bv, const float* __restrict__ bu,
    const float* __restrict__ bo, float* __restrict__ outp)
{
    extern __shared__ unsigned usm[];
    int tid = threadIdx.x;
    int w = tid >> 5, lane = tid & 31;
    int wm = w & 3, wn = w >> 2;
    int grp = lane >> 2, tig = lane & 3;

    int n0 = blockIdx.x * 128;
    int m0 = blockIdx.y * 128;

    const unsigned* A;
    const unsigned* Wt;
    const float* bias;
    float* out;
    if (MODE == 0) {
        int wsel = blockIdx.z;
        A    = g_ApU[wsel == 3 ? 0 : wsel];     // U uses query
        Wt   = g_WtU[wsel];
        bias = (wsel == 0) ? bq : (wsel == 1) ? bk : (wsel == 2) ? bv : bu;
        out  = g_P[wsel];
    } else {
        A = g_OhpU; Wt = g_WtU[4]; bias = bo; out = outp;
    }

    int r0f = tid >> 2,          s0f = (tid & 3) * 4;
    int r1f = (tid + 256) >> 2;
    const unsigned* pA0 = &A [(size_t)(m0 + r0f) * (D_ / 2) + s0f];
    const unsigned* pA1 = &A [(size_t)(m0 + r1f) * (D_ / 2) + s0f];
    const unsigned* pB0 = &Wt[(size_t)(n0 + r0f) * (D_ / 2) + s0f];
    const unsigned* pB1 = &Wt[(size_t)(n0 + r1f) * (D_ / 2) + s0f];
    unsigned base_u = s2u(usm);
    unsigned uA0 = base_u + (r0f * 16 + s0f) * 4;
    unsigned uA1 = base_u + (r1f * 16 + s0f) * 4;
    unsigned uB0 = uA0 + 2048 * 4;
    unsigned uB1 = uA1 + 2048 * 4;

    int aoff = (wm * 32 + grp) * 16 + tig * 4;
    int boff = (wn * 64 + grp) * 16 + tig * 4;

    float acc[2][8][4];
#pragma unroll
    for (int mt = 0; mt < 2; mt++)
#pragma unroll
        for (int nt = 0; nt < 8; nt++)
#pragma unroll
            for (int r = 0; r < 4; r++) acc[mt][nt][r] = 0.f;

#pragma unroll
    for (int p = 0; p < 3; p++) {
        cpa16u(uA0 + p * 16384, pA0); cpa16u(uA1 + p * 16384, pA1);
        cpa16u(uB0 + p * 16384, pB0); cpa16u(uB1 + p * 16384, pB1);
        cpa_commit();
        pA0 += 16; pA1 += 16; pB0 += 16; pB1 += 16;
    }

    int ktf = 48;
    for (int tt = 0; tt < 8; tt++) {
#pragma unroll
        for (int j = 0; j < 4; j++) {
            cpa_wait<2>();
            __syncthreads();

            if (ktf < D_ / 2) {
                const unsigned so = ((j + 3) & 3) * 16384;
                cpa16u(uA0 + so, pA0); cpa16u(uA1 + so, pA1);
                cpa16u(uB0 + so, pB0); cpa16u(uB1 + so, pB1);
                pA0 += 16; pA1 += 16; pB0 += 16; pB1 += 16;
            }
            cpa_commit();
            ktf += 16;

            const unsigned* As = usm + j * GSB2;
            const unsigned* Bs = As + 2048;

            uint4 av[2], ah[2];
#pragma unroll
            for (int mt = 0; mt < 2; mt++) {
                av[mt] = *(const uint4*)&As[aoff + mt * 256];
                ah[mt] = *(const uint4*)&As[aoff + mt * 256 + 128];
            }
            uint4 bw = *(const uint4*)&Bs[boff];
#pragma unroll
            for (int nt = 0; nt < 8; nt++) {
                uint4 bwn;
                if (nt < 7) bwn = *(const uint4*)&Bs[boff + (nt + 1) * 128];
#pragma unroll
                for (int mt = 0; mt < 2; mt++) {
                    mma_f16(acc[mt][nt][0], acc[mt][nt][1], acc[mt][nt][2], acc[mt][nt][3],
                            av[mt].x, ah[mt].x, av[mt].y, ah[mt].y, bw.x, bw.y);
                    mma_f16(acc[mt][nt][0], acc[mt][nt][1], acc[mt][nt][2], acc[mt][nt][3],
                            av[mt].z, ah[mt].z, av[mt].w, ah[mt].w, bw.z, bw.w);
                }
                bw = bwn;
            }
        }
    }

#pragma unroll
    for (int mt = 0; mt < 2; mt++) {
        int row = m0 + wm * 32 + mt * 16 + grp;
#pragma unroll
        for (int nt = 0; nt < 8; nt++) {
            int col = n0 + wn * 64 + nt * 8 + tig * 2;
            float2 b01 = make_float2(bias[col], bias[col + 1]);
            *(float2*)&out[(size_t)row * D_ + col] =
                make_float2(acc[mt][nt][0] + b01.x, acc[mt][nt][1] + b01.y);
            *(float2*)&out[(size_t)(row + 8) * D_ + col] =
                make_float2(acc[mt][nt][2] + b01.x, acc[mt][nt][3] + b01.y);
        }
    }
}

// ---------------- prep: tiled RoPE/gate -> f16 pairs ------------------------
__global__ __launch_bounds__(256) void prep_kernel(const int* __restrict__ action_ids)
{
    __shared__ float Vs[64 * 65];
    int tid = threadIdx.x;
    int l0 = blockIdx.x * 64;
    int bh = blockIdx.y;
    int b = bh >> 4, h = bh & 15;

#pragma unroll
    for (int u = 0; u < 4; u++) {
        int fid = tid + u * 256;
        int r = fid >> 4, c4 = (fid & 15) * 4;
        int l = l0 + r;
        int m = b * L_ + l;
        size_t base = (size_t)m * D_ + h * 64;

        float4 q4 = *(const float4*)&g_P[0][base + c4];
        float4 k4 = *(const float4*)&g_P[1][base + c4];
        float4 v4 = *(const float4*)&g_P[2][base + c4];
        float4 u4 = *(const float4*)&g_P[3][base + c4];
        float4 qp = *(const float4*)&g_P[0][base + (c4 ^ 32)];
        float4 kp = *(const float4*)&g_P[1][base + (c4 ^ 32)];

        int aid = action_ids[m];
        float4 gt = *(const float4*)&g_gtab[aid * D_ + h * 64 + c4];

        float ga0 = 1.f / (1.f + __expf(-(u4.x + gt.x)));
        float ga1 = 1.f / (1.f + __expf(-(u4.y + gt.y)));
        float ga2 = 1.f / (1.f + __expf(-(u4.z + gt.z)));
        float ga3 = 1.f / (1.f + __expf(-(u4.w + gt.w)));
        Vs[r * 65 + c4 + 0] = v4.x * ga0;
        Vs[r * 65 + c4 + 1] = v4.y * ga1;
        Vs[r * 65 + c4 + 2] = v4.z * ga2;
        Vs[r * 65 + c4 + 3] = v4.w * ga3;

        float sgn = (c4 < 32) ? -1.f : 1.f;
        int ci = l * 32 + (c4 >> 1);
        float c0 = g_cos[ci],     s0 = g_sin[ci];
        float c1 = g_cos[ci + 1], s1 = g_sin[ci + 1];

        float q0 = (q4.x * c0 + sgn * qp.x * s0) * QSCALE;
        float q1 = (q4.y * c0 + sgn * qp.y * s0) * QSCALE;
        float q2 = (q4.z * c1 + sgn * qp.z * s1) * QSCALE;
        float q3 = (q4.w * c1 + sgn * qp.w * s1) * QSCALE;
        float k0 = k4.x * c0 + sgn * kp.x * s0;
        float k1 = k4.y * c0 + sgn * kp.y * s0;
        float k2 = k4.z * c1 + sgn * kp.z * s1;
        float k3 = k4.w * c1 + sgn * kp.w * s1;

        size_t qb32 = ((size_t)bh * L_ + l) * 32;
        int pA = c4 >> 1;
        g_QpU[qb32 + perm32p(pA)]     = hfpack(q1, q0);
        g_QpU[qb32 + perm32p(pA + 1)] = hfpack(q3, q2);
        g_KpU[qb32 + perm32p(pA)]     = hfpack(k1, k0);
        g_KpU[qb32 + perm32p(pA + 1)] = hfpack(k3, k2);
    }
    __syncthreads();

    int w = tid >> 5, lane = tid & 31;
#pragma unroll
    for (int i = 0; i < 8; i++) {
        int dh = w * 8 + i;
        unsigned* orow = &g_VtU[((size_t)bh * DH_ + dh) * (L_ / 2) + (l0 >> 1)];
        unsigned val = hfpack(Vs[(2 * lane + 1) * 65 + dh], Vs[(2 * lane) * 65 + dh]);
        orow[perm32p(lane)] = val;
    }
}

// ---------------- tensor-core flash attention (f16, 3-stage pipeline) -------
#define KS_O 0
#define KV_STG (64*36)
#define VT_O (3*KV_STG)
#define BI_O (VT_O + 3*KV_STG)
#define MK_O (BI_O + 3*64)
#define SMEMF (MK_O + 3*256)

__device__ __forceinline__ void stage_fill(
    unsigned* usm, int s, int tid, int bh, int b, int q0, int k0)
{
    unsigned* KsS = usm + KS_O + s * KV_STG;
    unsigned* VtS = usm + VT_O + s * KV_STG;
#pragma unroll
    for (int u = 0; u < 2; u++) {
        int cid = tid + u * 256;
        int row = cid >> 3, seg = (cid & 7) * 4;
        cpa16(&KsS[row * 36 + seg],
              &g_KpU[((size_t)bh * L_ + k0 + row) * 32 + seg]);
        cpa16(&VtS[row * 36 + seg],
              &g_VtU[((size_t)bh * DH_ + row) * (L_ / 2) + (k0 >> 1) + seg]);
    }
    if (tid < 16)
        cpa16(usm + BI_O + s * 64 + tid * 4, &g_bias[(size_t)bh * L_ + k0 + tid * 4]);
    if (tid < 128) {
        unsigned* mdst = usm + MK_O + s * 256 + tid * 2;
        cpa8(mdst, &g_mbits[((size_t)b * L_ + q0 + tid) * (L_ / 32) + (k0 >> 5)]);
    }
}

__global__ __launch_bounds__(256, 2) void attn_kernel() {
    extern __shared__ unsigned usm[];

    int tid = threadIdx.x;
    int w = tid >> 5, lane = tid & 31;
    int grp = lane >> 2, tig = lane & 3;
    int q0 = blockIdx.x * QT_;
    int bh = blockIdx.y;
    int b = bh >> 4, h = bh & 15;
    int w16 = w * 16;

    unsigned af[4][4];
    {
        const unsigned* q0p = &g_QpU[((size_t)bh * L_ + q0 + w16 + grp) * 32 + tig * 8];
        const unsigned* q1p = &g_QpU[((size_t)bh * L_ + q0 + w16 + grp + 8) * 32 + tig * 8];
        uint4 qa = *(const uint4*)q0p;
        uint4 qb = *(const uint4*)(q0p + 4);
        uint4 qc = *(const uint4*)q1p;
        uint4 qd = *(const uint4*)(q1p + 4);
        af[0][0] = qa.x; af[0][1] = qc.x; af[0][2] = qa.y; af[0][3] = qc.y;
        af[1][0] = qa.z; af[1][1] = qc.z; af[1][2] = qa.w; af[1][3] = qc.w;
        af[2][0] = qb.x; af[2][1] = qd.x; af[2][2] = qb.y; af[2][3] = qd.y;
        af[3][0] = qb.z; af[3][1] = qd.z; af[3][2] = qb.w; af[3][3] = qd.w;
    }

    float o[8][4];
#pragma unroll
    for (int nf = 0; nf < 8; nf++)
#pragma unroll
        for (int r = 0; r < 4; r++) o[nf][r] = 0.f;
    float l0r = 0.f, l1r = 0.f;

    stage_fill(usm, 0, tid, bh, b, q0, 0);
    cpa_commit();
    stage_fill(usm, 1, tid, bh, b, q0, KT_);
    cpa_commit();

    int cs = 0, fs = 2;
    for (int t = 0; t < NT_; t++) {
        if (t + 2 < NT_) {
            stage_fill(usm, fs, tid, bh, b, q0, (t + 2) * KT_);
        }
        cpa_commit();               // unconditional: keeps group counting exact
        fs = (fs == 2) ? 0 : fs + 1;
        cpa_wait<2>();
        __syncthreads();

        const unsigned* KsS = usm + KS_O + cs * KV_STG;
        const unsigned* VtU = usm + VT_O + cs * KV_STG;
        const float* biasS = (const float*)(usm + BI_O + cs * 64);
        const unsigned* mk = usm + MK_O + cs * 256;
        cs = (cs == 2) ? 0 : cs + 1;

        unsigned mr0lo = mk[(w16 + grp) * 2],     mr0hi = mk[(w16 + grp) * 2 + 1];
        unsigned mr1lo = mk[(w16 + grp + 8) * 2], mr1hi = mk[(w16 + grp + 8) * 2 + 1];

        // ---- scores (f16 m16n8k16), rolling K prefetch ----
        float sc[8][4];
        uint4 kv1 = *(const uint4*)&KsS[grp * 36 + tig * 8];
        uint4 kv2 = *(const uint4*)&KsS[grp * 36 + tig * 8 + 4];
#pragma unroll
        for (int nf = 0; nf < 8; nf++) {
            uint4 n1, n2;
            if (nf < 7) {
                const unsigned* kpn = &KsS[((nf + 1) * 8 + grp) * 36 + tig * 8];
                n1 = *(const uint4*)kpn;
                n2 = *(const uint4*)(kpn + 4);
            }
            sc[nf][0] = 0.f; sc[nf][1] = 0.f; sc[nf][2] = 0.f; sc[nf][3] = 0.f;
            mma_f16(sc[nf][0], sc[nf][1], sc[nf][2], sc[nf][3],
                    af[0][0], af[0][1], af[0][2], af[0][3], kv1.x, kv1.y);
            mma_f16(sc[nf][0], sc[nf][1], sc[nf][2], sc[nf][3],
                    af[1][0], af[1][1], af[1][2], af[1][3], kv1.z, kv1.w);
            mma_f16(sc[nf][0], sc[nf][1], sc[nf][2], sc[nf][3],
                    af[2][0], af[2][1], af[2][2], af[2][3], kv2.x, kv2.y);
            mma_f16(sc[nf][0], sc[nf][1], sc[nf][2], sc[nf][3],
                    af[3][0], af[3][1], af[3][2], af[3][3], kv2.z, kv2.w);
            kv1 = n1; kv2 = n2;
        }

        // ---- softmax -> PV, chunk-interleaved; fast path for all-ones mask ----
        bool full = (mr0lo & mr0hi & mr1lo & mr1hi) == 0xffffffffu;
        if (full) {
#pragma unroll
            for (int c = 0; c < 4; c++) {
                int nA = 2 * c, nB = 2 * c + 1;
                float2 bbA = *(const float2*)&biasS[nA * 8 + tig * 2];
                float2 bbB = *(const float2*)&biasS[nB * 8 + tig * 2];
                float pA0 = ex2(sc[nA][0] + bbA.x);
                float pA1 = ex2(sc[nA][1] + bbA.y);
                float pA2 = ex2(sc[nA][2] + bbA.x);
                float pA3 = ex2(sc[nA][3] + bbA.y);
                float pB0 = ex2(sc[nB][0] + bbB.x);
                float pB1 = ex2(sc[nB][1] + bbB.y);
                float pB2 = ex2(sc[nB][2] + bbB.x);
                float pB3 = ex2(sc[nB][3] + bbB.y);
                l0r += (pA0 + pA1) + (pB0 + pB1);
                l1r += (pA2 + pA3) + (pB2 + pB3);
                unsigned f0 = hfpack(pA1, pA0);
                unsigned f1 = hfpack(pA3, pA2);
                unsigned f2 = hfpack(pB1, pB0);
                unsigned f3 = hfpack(pB3, pB2);
#pragma unroll
                for (int nf = 0; nf < 8; nf++) {
                    uint2 v2 = *(const uint2*)&VtU[(nf * 8 + grp) * 36 + tig * 8 + 2 * c];
                    mma_f16(o[nf][0], o[nf][1], o[nf][2], o[nf][3],
                            f0, f1, f2, f3, v2.x, v2.y);
                }
            }
        } else {
#pragma unroll
            for (int c = 0; c < 4; c++) {
                int nA = 2 * c, nB = 2 * c + 1;
                float2 bbA = *(const float2*)&biasS[nA * 8 + tig * 2];
                float2 bbB = *(const float2*)&biasS[nB * 8 + tig * 2];
                int bpA = (nA & 3) * 8 + tig * 2;
                int bpB = (nB & 3) * 8 + tig * 2;
                unsigned mA0 = ((nA < 4) ? mr0lo : mr0hi) >> bpA;
                unsigned mA1 = ((nA < 4) ? mr1lo : mr1hi) >> bpA;
                unsigned mB0 = ((nB < 4) ? mr0lo : mr0hi) >> bpB;
                unsigned mB1 = ((nB < 4) ? mr1lo : mr1hi) >> bpB;

                float pA0 = (mA0 & 1u) ? ex2(sc[nA][0] + bbA.x) : 0.f;
                float pA1 = (mA0 & 2u) ? ex2(sc[nA][1] + bbA.y) : 0.f;
                float pA2 = (mA1 & 1u) ? ex2(sc[nA][2] + bbA.x) : 0.f;
                float pA3 = (mA1 & 2u) ? ex2(sc[nA][3] + bbA.y) : 0.f;
                float pB0 = (mB0 & 1u) ? ex2(sc[nB][0] + bbB.x) : 0.f;
                float pB1 = (mB0 & 2u) ? ex2(sc[nB][1] + bbB.y) : 0.f;
                float pB2 = (mB1 & 1u) ? ex2(sc[nB][2] + bbB.x) : 0.f;
                float pB3 = (mB1 & 2u) ? ex2(sc[nB][3] + bbB.y) : 0.f;

                l0r += (pA0 + pA1) + (pB0 + pB1);
                l1r += (pA2 + pA3) + (pB2 + pB3);
                unsigned f0 = hfpack(pA1, pA0);
                unsigned f1 = hfpack(pA3, pA2);
                unsigned f2 = hfpack(pB1, pB0);
                unsigned f3 = hfpack(pB3, pB2);
#pragma unroll
                for (int nf = 0; nf < 8; nf++) {
                    uint2 v2 = *(const uint2*)&VtU[(nf * 8 + grp) * 36 + tig * 8 + 2 * c];
                    mma_f16(o[nf][0], o[nf][1], o[nf][2], o[nf][3],
                            f0, f1, f2, f3, v2.x, v2.y);
                }
            }
        }
        __syncthreads();
    }

    // ---- final row-sum reduction across the quad, then normalize ----
    l0r += __shfl_xor_sync(0xffffffffu, l0r, 1);
    l0r += __shfl_xor_sync(0xffffffffu, l0r, 2);
    l1r += __shfl_xor_sync(0xffffffffu, l1r, 1);
    l1r += __shfl_xor_sync(0xffffffffu, l1r, 2);
    float inv0 = 1.f / l0r, inv1 = 1.f / l1r;

    int l0i = q0 + w16 + grp;
    size_t r0 = ((size_t)(b * L_) + l0i) * (D_ / 2) + h * 32;
    size_t r1 = ((size_t)(b * L_) + l0i + 8) * (D_ / 2) + h * 32;
#pragma unroll
    for (int nf = 0; nf < 8; nf++) {
        int p = nf * 4 + tig;
        int pos = (p & 16) + permg(p & 15);
        g_OhpU[r0 + pos] = hfpack(o[nf][1] * inv0, o[nf][0] * inv0);
        g_OhpU[r1 + pos] = hfpack(o[nf][3] * inv1, o[nf][2] * inv1);
    }
}

// ---------------- launch -----------------------------------------------------
extern "C" void kernel_launch(void* const* d_in, const int* in_sizes, int n_in,
                              void* d_out, int out_size)
{
    const float* query      = (const float*)d_in[0];
    const float* key        = (const float*)d_in[1];
    const float* value      = (const float*)d_in[2];
    const unsigned char* am = (const unsigned char*)d_in[3];
    const int*   action_ids = (const int*)d_in[4];
    const int*   time_delta = (const int*)d_in[5];
    const float* Wq = (const float*)d_in[6];
    const float* bq = (const float*)d_in[7];
    const float* Wk = (const float*)d_in[8];
    const float* bk = (const float*)d_in[9];
    const float* Wv = (const float*)d_in[10];
    const float* bv = (const float*)d_in[11];
    const float* Wu = (const float*)d_in[12];
    const float* bu = (const float*)d_in[13];
    const float* Wo = (const float*)d_in[14];
    const float* bo = (const float*)d_in[15];
    const float* action_emb = (const float*)d_in[16];
    const float* Wap = (const float*)d_in[17];
    const float* bap = (const float*)d_in[18];
    const float* td_emb  = (const float*)d_in[19];
    const float* td_gate = (const float*)d_in[20];
    float* out = (float*)d_out;

    const int gemm_smem = 4 * GSB2 * (int)sizeof(unsigned);
    cudaFuncSetAttribute(gemm4_kernel<0>, cudaFuncAttributeMaxDynamicSharedMemorySize, gemm_smem);
    cudaFuncSetAttribute(gemm4_kernel<1>, cudaFuncAttributeMaxDynamicSharedMemorySize, gemm_smem);

    // launch order: mega_pre(1), gemm<0>(2), prep(3), attn(4 <- profiled), gemm<1>(5)
    mega_pre_kernel<<<MEGA_B, 256>>>(query, key, value, Wq, Wk, Wv, Wu, Wo,
                                     time_delta, td_emb, td_gate,
                                     action_emb, Wap, bap, am);

    gemm4_kernel<0><<<dim3(8, 32, 4), 256, gemm_smem>>>(bq, bk, bv, bu, bo, nullptr);

    prep_kernel<<<dim3(L_ / 64, B_ * H_), 256>>>(action_ids);

    const int attn_smem = SMEMF * (int)sizeof(unsigned);
    cudaFuncSetAttribute(attn_kernel, cudaFuncAttributeMaxDynamicSharedMemorySize, attn_smem);
    attn_kernel<<<dim3(L_ / QT_, B_ * H_), 256, attn_smem>>>();

    gemm4_kernel<1><<<dim3(8, 32, 1), 256, gemm_smem>>>(bq, bk, bv, bu, bo, out);
}